// round 11
// baseline (speedup 1.0000x reference)
#include <cuda_runtime.h>
#include <cuda_bf16.h>

// I_MLP_7206955123212 — B=2^21 independent 10-step tiny-MLP rollouts.
// R10 winner (RPT=3, smem weights, zero spill) + composite tanh table:
// the fc-pred path needs tanh(z) AND tanh(tanh(z)) (err term) — one smem
// float4 lerp table over z in [-8,8] returns both with a single LDS.128,
// removing 4 of 24 MUFU sites per row-step (MUFU is the measured 135us wall).

__device__ __forceinline__ float tanh_fast(float x) {
    float y; asm("tanh.approx.f32 %0,%1;" : "=f"(y) : "f"(x)); return y;
}
__device__ __forceinline__ float sqrt_fast(float x) {
    float y; asm("sqrt.approx.f32 %0,%1;" : "=f"(y) : "f"(x)); return y;
}

// g_w layout (floats):
//  [0..19]    pred: Wf00,Wf01,Wf10,Wf11, Wh00,Wh01,Wh10,Wh11,
//                   WfS(4), WhS(4), Bf0,Bf1,Bh0,Bh1
//  [20..51]   rc1_w (j*4+k)       [52..59]   rc1_b
//  [60..123]  rc2_w (j*8+k)       [124..131] rc2_b
//  [132..147] rc3_w (r*8+k)       [148..149] rc3_b
__device__ float g_w[160];
// Composite table: entry i covers z in [x_i, x_{i+1}], x_i = -8 + 16*i/1023.
//  .x = tanh(x_i)  .y = tanh(x_{i+1})-tanh(x_i)
//  .z = tanh(tanh(x_i))  .w = delta of same
__device__ float4 g_tab4[1024];

__global__ void prep_kernel(const float* __restrict__ fc1_w, const float* __restrict__ fc1_b,
                            const float* __restrict__ fc2_w, const float* __restrict__ fc2_b,
                            const float* __restrict__ rc1_w, const float* __restrict__ rc1_b,
                            const float* __restrict__ rc2_w, const float* __restrict__ rc2_b,
                            const float* __restrict__ rc3_w, const float* __restrict__ rc3_b,
                            const float* __restrict__ hf1_w, const float* __restrict__ hf1_b,
                            const float* __restrict__ hf2_w, const float* __restrict__ hf2_b)
{
    const int tid = threadIdx.x;

    // Parallel table build (all 1024 threads).
    {
        const float x  = -8.f + 16.f * (float)tid / 1023.f;
        const float xn = -8.f + 16.f * (float)(tid + 1) / 1023.f;
        const float v  = tanhf(x),  g  = tanhf(v);
        const float vn = tanhf(xn), gn = tanhf(vn);
        float4 e;
        e.x = v;  e.y = (tid < 1023) ? (vn - v) : 0.f;
        e.z = g;  e.w = (tid < 1023) ? (gn - g) : 0.f;
        g_tab4[tid] = e;
    }

    if (tid != 0) return;

    // Fuse fc2@fc1 and hf2@hf1 (no activation between) into 2x4 affines.
    float Wf[2][4], Wh[2][4], Bf[2], Bh[2];
    for (int r = 0; r < 2; ++r) {
        for (int k = 0; k < 4; ++k) {
            float af = 0.f, ah = 0.f;
            for (int j = 0; j < 4; ++j) {
                af = fmaf(fc2_w[r * 4 + j], fc1_w[j * 4 + k], af);
                ah = fmaf(hf2_w[r * 4 + j], hf1_w[j * 4 + k], ah);
            }
            Wf[r][k] = af; Wh[r][k] = ah;
        }
        float bf = fc2_b[r], bh = hf2_b[r];
        for (int j = 0; j < 4; ++j) {
            bf = fmaf(fc2_w[r * 4 + j], fc1_b[j], bf);
            bh = fmaf(hf2_w[r * 4 + j], hf1_b[j], bh);
        }
        Bf[r] = bf; Bh[r] = bh;
    }
    g_w[0] = Wf[0][0]; g_w[1] = Wf[0][1]; g_w[2] = Wf[1][0]; g_w[3] = Wf[1][1];
    g_w[4] = Wh[0][0]; g_w[5] = Wh[0][1]; g_w[6] = Wh[1][0]; g_w[7] = Wh[1][1];
    g_w[8]  = Wf[0][2]; g_w[9]  = Wf[0][3]; g_w[10] = Wf[1][2]; g_w[11] = Wf[1][3];
    g_w[12] = Wh[0][2]; g_w[13] = Wh[0][3]; g_w[14] = Wh[1][2]; g_w[15] = Wh[1][3];
    g_w[16] = Bf[0]; g_w[17] = Bf[1]; g_w[18] = Bh[0]; g_w[19] = Bh[1];

    for (int i = 0; i < 32; ++i) g_w[20 + i]  = rc1_w[i];
    for (int i = 0; i < 8;  ++i) g_w[52 + i]  = rc1_b[i];
    for (int i = 0; i < 64; ++i) g_w[60 + i]  = rc2_w[i];
    for (int i = 0; i < 8;  ++i) g_w[124 + i] = rc2_b[i];
    for (int i = 0; i < 16; ++i) g_w[132 + i] = rc3_w[i];
    for (int i = 0; i < 2;  ++i) g_w[148 + i] = rc3_b[i];
}

#define RPT 3

__global__ void __launch_bounds__(128, 4)
rollout_kernel(const float* __restrict__ s_star, const float* __restrict__ s0,
               float* __restrict__ out, int B)
{
    // smem: s_pred[20], rc blocks in s_w (16B aligned), composite table.
    __shared__ float s_pred[20];
    __shared__ __align__(16) float s_w[132];
    __shared__ __align__(16) float4 s_tab[1024];
    for (int i = threadIdx.x; i < 150; i += blockDim.x) {
        if (i < 20) s_pred[i] = g_w[i];
        else        s_w[i - 20] = g_w[i];
    }
    for (int i = threadIdx.x; i < 1024; i += blockDim.x)
        s_tab[i] = g_tab4[i];
    __syncthreads();

    const float4* __restrict__ s4_rc1 = reinterpret_cast<const float4*>(s_w + 0);
    const float*  __restrict__ s_rc1b = s_w + 32;
    const float4* __restrict__ s4_rc2 = reinterpret_cast<const float4*>(s_w + 40);
    const float*  __restrict__ s_rc2b = s_w + 104;
    const float4* __restrict__ s4_rc3 = reinterpret_cast<const float4*>(s_w + 112);
    const float*  __restrict__ s_rc3b = s_w + 128;

    const int base = (blockIdx.x * blockDim.x + threadIdx.x) * RPT;
    if (base >= B) return;

    const float Wf00 = s_pred[0], Wf01 = s_pred[1], Wf10 = s_pred[2], Wf11 = s_pred[3];
    const float Wh00 = s_pred[4], Wh01 = s_pred[5], Wh10 = s_pred[6], Wh11 = s_pred[7];

    float sx[RPT], sy[RPT], ssx[RPT], ssy[RPT], err[RPT];
    float Cf0[RPT], Cf1[RPT], Ch0[RPT], Ch1[RPT];
    #pragma unroll
    for (int r = 0; r < RPT; ++r) {
        const int i = (base + r < B) ? base + r : B - 1;
        const float2 ssv = reinterpret_cast<const float2*>(s_star)[i];
        const float2 s0v = reinterpret_cast<const float2*>(s0)[i];
        ssx[r] = ssv.x; ssy[r] = ssv.y;
        sx[r] = s0v.x;  sy[r] = s0v.y;  err[r] = 0.f;
        Cf0[r] = fmaf(s_pred[8],  ssv.x, fmaf(s_pred[9],  ssv.y, s_pred[16]));
        Cf1[r] = fmaf(s_pred[10], ssv.x, fmaf(s_pred[11], ssv.y, s_pred[17]));
        Ch0[r] = fmaf(s_pred[12], ssv.x, fmaf(s_pred[13], ssv.y, s_pred[18]));
        Ch1[r] = fmaf(s_pred[14], ssv.x, fmaf(s_pred[15], ssv.y, s_pred[19]));
    }

    // Step loop NOT unrolled: keeps smem weight loads inside the loop body
    // (hoisting them into long-lived registers is what causes spills).
    #pragma unroll 1
    for (int t = 0; t < 10; ++t) {
        float ah0[RPT], ah1[RPT];
        #pragma unroll
        for (int r = 0; r < RPT; ++r) {
            // fc pred net via composite table: one LDS.128 per neuron gives
            // tanh(z) (state path) + tanh(tanh(z)) (err term). z is clamped to
            // [-8,8] where tanh saturates to +/-1 within 2.3e-7.
            const float z0 = fmaf(Wf00, sx[r], fmaf(Wf01, sy[r], Cf0[r]));
            const float z1 = fmaf(Wf10, sx[r], fmaf(Wf11, sy[r], Cf1[r]));
            float t0 = fminf(fmaxf(fmaf(z0, 63.9375f, 511.5f), 0.f), 1022.99f);
            float t1 = fminf(fmaxf(fmaf(z1, 63.9375f, 511.5f), 0.f), 1022.99f);
            const int i0 = __float2int_rd(t0);
            const int i1 = __float2int_rd(t1);
            const float fr0 = t0 - __int2float_rn(i0);
            const float fr1 = t1 - __int2float_rn(i1);
            const float4 e0 = s_tab[i0];
            const float4 e1 = s_tab[i1];
            ah0[r] = fmaf(fr0, e0.y, e0.x);
            ah1[r] = fmaf(fr1, e1.y, e1.x);

            // detached net: MUFU tanh (ahh used once, right here)
            const float ag0 = tanh_fast(fmaf(Wh00, sx[r], fmaf(Wh01, sy[r], Ch0[r])));
            const float ag1 = tanh_fast(fmaf(Wh10, sx[r], fmaf(Wh11, sy[r], Ch1[r])));
            const float d0 = ah0[r] - ag0, d1 = ah1[r] - ag1;
            float e = err[r];
            e += sqrt_fast(fmaf(d0, d0, d1 * d1));
            // err tanh terms come free from the table (.z/.w lanes)
            e += fmaf(fr0, e0.w, e0.z) + fmaf(fr1, e1.w, e1.z);
            e += sqrt_fast(fmaf(ah0[r], ah0[r], ah1[r] * ah1[r]));
            err[r] = e;
        }

        // rc1: [s, ah] -> 8  (weights broadcast from smem, shared by all rows)
        float h1[RPT][8];
        #pragma unroll
        for (int j = 0; j < 8; ++j) {
            const float4 w = s4_rc1[j];
            const float  b = s_rc1b[j];
            #pragma unroll
            for (int r = 0; r < RPT; ++r)
                h1[r][j] = tanh_fast(fmaf(w.x, sx[r],
                                     fmaf(w.y, sy[r],
                                     fmaf(w.z, ah0[r],
                                     fmaf(w.w, ah1[r], b)))));
        }

        // rc2: 8 -> 8
        float h2[RPT][8];
        #pragma unroll
        for (int j = 0; j < 8; ++j) {
            const float4 wa = s4_rc2[2 * j];
            const float4 wb = s4_rc2[2 * j + 1];
            const float  b  = s_rc2b[j];
            #pragma unroll
            for (int r = 0; r < RPT; ++r) {
                float a = fmaf(wa.x, h1[r][0], fmaf(wa.y, h1[r][1],
                          fmaf(wa.z, h1[r][2], fmaf(wa.w, h1[r][3], b))));
                a = fmaf(wb.x, h1[r][4], fmaf(wb.y, h1[r][5],
                    fmaf(wb.z, h1[r][6], fmaf(wb.w, h1[r][7], a))));
                h2[r][j] = tanh_fast(a);
            }
        }

        // rc3: 8 -> 2, state update, tracking error
        {
            const float4 wa0 = s4_rc3[0], wa1 = s4_rc3[1];
            const float4 wb0 = s4_rc3[2], wb1 = s4_rc3[3];
            const float  b30 = s_rc3b[0], b31 = s_rc3b[1];
            #pragma unroll
            for (int r = 0; r < RPT; ++r) {
                float ar0 = fmaf(wa0.x, h2[r][0], fmaf(wa0.y, h2[r][1],
                            fmaf(wa0.z, h2[r][2], fmaf(wa0.w, h2[r][3], b30))));
                ar0 = fmaf(wa1.x, h2[r][4], fmaf(wa1.y, h2[r][5],
                      fmaf(wa1.z, h2[r][6], fmaf(wa1.w, h2[r][7], ar0))));
                float ar1 = fmaf(wb0.x, h2[r][0], fmaf(wb0.y, h2[r][1],
                            fmaf(wb0.z, h2[r][2], fmaf(wb0.w, h2[r][3], b31))));
                ar1 = fmaf(wb1.x, h2[r][4], fmaf(wb1.y, h2[r][5],
                      fmaf(wb1.z, h2[r][6], fmaf(wb1.w, h2[r][7], ar1))));
                sx[r] = fmaf(0.1f, ar0, sx[r]);
                sy[r] = fmaf(0.1f, ar1, sy[r]);

                const float dx = sx[r] - ssx[r], dy = sy[r] - ssy[r];
                err[r] += fmaf(dx, dx, dy * dy);
            }
        }
    }

    #pragma unroll
    for (int r = 0; r < RPT; ++r)
        if (base + r < B) out[base + r] = err[r];
}

extern "C" void kernel_launch(void* const* d_in, const int* in_sizes, int n_in,
                              void* d_out, int out_size)
{
    const float* s_star = (const float*)d_in[0];
    const float* s0     = (const float*)d_in[1];
    const float* fc1_w  = (const float*)d_in[2];
    const float* fc1_b  = (const float*)d_in[3];
    const float* fc2_w  = (const float*)d_in[4];
    const float* fc2_b  = (const float*)d_in[5];
    const float* rc1_w  = (const float*)d_in[6];
    const float* rc1_b  = (const float*)d_in[7];
    const float* rc2_w  = (const float*)d_in[8];
    const float* rc2_b  = (const float*)d_in[9];
    const float* rc3_w  = (const float*)d_in[10];
    const float* rc3_b  = (const float*)d_in[11];
    const float* hf1_w  = (const float*)d_in[12];
    const float* hf1_b  = (const float*)d_in[13];
    const float* hf2_w  = (const float*)d_in[14];
    const float* hf2_b  = (const float*)d_in[15];
    float* out = (float*)d_out;

    const int B = out_size;

    prep_kernel<<<1, 1024>>>(fc1_w, fc1_b, fc2_w, fc2_b,
                             rc1_w, rc1_b, rc2_w, rc2_b, rc3_w, rc3_b,
                             hf1_w, hf1_b, hf2_w, hf2_b);

    const int threads = 128;
    const int rows_per_block = threads * RPT;
    const int blocks = (B + rows_per_block - 1) / rows_per_block;
    rollout_kernel<<<blocks, threads>>>(s_star, s0, out, B);
}